// round 7
// baseline (speedup 1.0000x reference)
#include <cuda_runtime.h>

#define T_STEPS 750
#define B_TOT   1024
#define HID     100
#define KDIM    104      // 100 recurrent + 4 input-drive rows
#define NQUAD   (KDIM / 4)   // 26
#define BTILE   4
#define NTHREADS 128
#define NBLOCKS (B_TOT / BTILE)   // 256
#define RSTRIDE 112      // padded row stride for Rt (floats), 16B-aligned
#define ALPHA   0.01f
#define NSTD    0.1f

__device__ __forceinline__ float tanh_fast(float x) {
    float y;
    asm("tanh.approx.f32 %0, %1;" : "=f"(y) : "f"(x));
    return y;
}
__device__ __forceinline__ unsigned long long pack_pair(float lo, float hi) {
    unsigned long long r;
    asm("mov.b64 %0, {%1, %2};" : "=l"(r) : "f"(lo), "f"(hi));
    return r;
}
__device__ __forceinline__ void ffma2(unsigned long long& d,
                                      unsigned long long a,
                                      unsigned long long b) {
    asm("fma.rn.f32x2 %0, %1, %2, %0;" : "+l"(d) : "l"(a), "l"(b));
}
__device__ __forceinline__ float2 unpack2(unsigned long long v) {
    float2 f;
    asm("mov.b64 {%0, %1}, %2;" : "=f"(f.x), "=f"(f.y) : "l"(v));
    return f;
}

// One RNN step.  Rt is transposed: Rt[b][j] (j contiguous).
// Jp[k] = (Jrow[2k], Jrow[2k+1]) packed once at init -> no per-step packing.
__device__ __forceinline__ void rnn_step(
    int tcur, int i, int b0,
    float (&x)[BTILE], const unsigned long long (&Jp)[KDIM / 2], float ci,
    const float (&ncur)[BTILE], float ucur,
    float (&nnext)[BTILE], float& unext,
    float (&Rt)[BTILE][RSTRIDE],
    const float* __restrict__ noise,
    const float* __restrict__ input_seq)
{
    // Phase 1: publish r = tanh(x) into column i of each batch row (4 STS.32,
    // lane-consecutive -> conflict-free); u values to columns 100..103.
    if (i < HID) {
        Rt[0][i] = tanh_fast(x[0]);
        Rt[1][i] = tanh_fast(x[1]);
        Rt[2][i] = tanh_fast(x[2]);
        Rt[3][i] = tanh_fast(x[3]);
    }
    if (i < 16) Rt[i >> 2][HID + (i & 3)] = ucur;   // b = i>>2, c = i&3
    __syncthreads();

    // Prefetch next step's noise + input (one full step ahead of use)
    const int tn = (tcur + 1 < T_STEPS) ? (tcur + 1) : tcur;
    {
        const float* np = noise + ((size_t)tn * B_TOT + b0) * HID + i;
#pragma unroll
        for (int b = 0; b < BTILE; b++)
            nnext[b] = (i < HID) ? np[b * HID] : 0.0f;
        if (i < 16)
            unext = input_seq[((size_t)tn * B_TOT + b0 + (i >> 2)) * 4 + (i & 3)];
    }

    // Phase 2: acc[b] (packed even/odd j partial sums):
    //   acc[b] += (J[j],J[j+1]) * (R[j][b],R[j+1][b])
    // One LDS.128 per (b, quad) gives two packed j-pairs.
    unsigned long long acc0 = 0ull, acc1 = 0ull, acc2 = 0ull, acc3 = 0ull;
#pragma unroll
    for (int q = 0; q < NQUAD; q++) {
        ulonglong2 r0 = *(const ulonglong2*)&Rt[0][4 * q];
        ulonglong2 r1 = *(const ulonglong2*)&Rt[1][4 * q];
        ulonglong2 r2 = *(const ulonglong2*)&Rt[2][4 * q];
        ulonglong2 r3 = *(const ulonglong2*)&Rt[3][4 * q];
        const unsigned long long ja = Jp[2 * q];
        const unsigned long long jb = Jp[2 * q + 1];
        ffma2(acc0, r0.x, ja);
        ffma2(acc1, r1.x, ja);
        ffma2(acc2, r2.x, ja);
        ffma2(acc3, r3.x, ja);
        ffma2(acc0, r0.y, jb);
        ffma2(acc1, r1.y, jb);
        ffma2(acc2, r2.y, jb);
        ffma2(acc3, r3.y, jb);
    }
    __syncthreads();   // all reads of Rt done before next step overwrites it

    // Phase 3: y[b] = lo+hi of acc[b]; x update in registers.
    float2 a0 = unpack2(acc0), a1 = unpack2(acc1);
    float2 a2 = unpack2(acc2), a3 = unpack2(acc3);
    float y[BTILE] = { a0.x + a0.y, a1.x + a1.y, a2.x + a2.y, a3.x + a3.y };
#pragma unroll
    for (int b = 0; b < BTILE; b++) {
        x[b] = fmaf(1.0f - ALPHA, x[b],
               fmaf(ALPHA, y[b],
               fmaf(ALPHA * NSTD, ncur[b], ci)));
    }
}

__global__ void __launch_bounds__(NTHREADS, 2)
rnn_kernel(const float* __restrict__ input_seq,
           const float* __restrict__ noise,
           const float* __restrict__ J_w,
           const float* __restrict__ Bmat,
           const float* __restrict__ c_x,
           const float* __restrict__ Wout_w,
           const float* __restrict__ Wout_b,
           float* __restrict__ out)
{
    __shared__ __align__(16) float Rt[BTILE][RSTRIDE];
    __shared__ float warp_part[4][BTILE];   // epilogue partials

    const int i  = threadIdx.x;            // state row owned by this thread
    const int b0 = blockIdx.x * BTILE;     // batch slice base

    // Row i of [J ; Bmat^T], packed as j-pairs, held permanently in registers.
    unsigned long long Jp[KDIM / 2];
#pragma unroll
    for (int k = 0; k < KDIM / 2; k++) {
        float lo = 0.0f, hi = 0.0f;
        if (i < HID) {
            const int j0 = 2 * k, j1 = 2 * k + 1;
            lo = (j0 < HID) ? J_w[i * HID + j0] : Bmat[(j0 - HID) * HID + i];
            hi = (j1 < HID) ? J_w[i * HID + j1] : Bmat[(j1 - HID) * HID + i];
        }
        Jp[k] = pack_pair(lo, hi);
    }
    const float ci = (i < HID) ? (ALPHA * c_x[i]) : 0.0f;

    float x[BTILE];
#pragma unroll
    for (int b = 0; b < BTILE; b++) x[b] = 0.0f;

    // Preload t=0 noise + input into buffer A
    float nA[BTILE], nB[BTILE];
    float uA = 0.0f, uB = 0.0f;
    {
        const float* np = noise + (size_t)b0 * HID + i;
#pragma unroll
        for (int b = 0; b < BTILE; b++)
            nA[b] = (i < HID) ? np[b * HID] : 0.0f;
        if (i < 16)
            uA = input_seq[((size_t)b0 + (i >> 2)) * 4 + (i & 3)];
    }

    // Main scan, unrolled by 2 for register double-buffering of noise/input
    for (int t = 0; t < T_STEPS; t += 2) {
        rnn_step(t,     i, b0, x, Jp, ci, nA, uA, nB, uB, Rt, noise, input_seq);
        rnn_step(t + 1, i, b0, x, Jp, ci, nB, uB, nA, uA, Rt, noise, input_seq);
    }

    // Epilogue: out[b] = tanh(x_final[b]) . Wout + bias.
    // Deterministic: butterfly shuffle within warp, fixed-order cross-warp sum.
    {
        const float w = (i < HID) ? Wout_w[i] : 0.0f;
        float part[BTILE];
#pragma unroll
        for (int b = 0; b < BTILE; b++)
            part[b] = (i < HID) ? w * tanhf(x[b]) : 0.0f;
#pragma unroll
        for (int off = 16; off > 0; off >>= 1) {
#pragma unroll
            for (int b = 0; b < BTILE; b++)
                part[b] += __shfl_xor_sync(0xFFFFFFFFu, part[b], off);
        }
        const int warp = i >> 5;
        if ((i & 31) == 0) {
#pragma unroll
            for (int b = 0; b < BTILE; b++)
                warp_part[warp][b] = part[b];
        }
        __syncthreads();
        if (i < BTILE) {
            float s = warp_part[0][i] + warp_part[1][i]
                    + warp_part[2][i] + warp_part[3][i];
            out[b0 + i] = s + Wout_b[0];
        }
    }
}

extern "C" void kernel_launch(void* const* d_in, const int* in_sizes, int n_in,
                              void* d_out, int out_size)
{
    const float* input_seq = (const float*)d_in[0];  // [750,1024,4]
    const float* noise     = (const float*)d_in[1];  // [750,1024,100]
    const float* J_w       = (const float*)d_in[2];  // [100,100]
    const float* Bmat      = (const float*)d_in[3];  // [4,100]
    const float* c_x       = (const float*)d_in[4];  // [100]
    const float* Wout_w    = (const float*)d_in[5];  // [1,100]
    const float* Wout_b    = (const float*)d_in[6];  // [1]
    float* out = (float*)d_out;                      // [1024]

    rnn_kernel<<<NBLOCKS, NTHREADS>>>(
        input_seq, noise, J_w, Bmat, c_x, Wout_w, Wout_b, out);
}

// round 9
// speedup vs baseline: 1.0712x; 1.0712x over previous
#include <cuda_runtime.h>

#define T_STEPS 750
#define B_TOT   1024
#define HID     100
#define KDIM    104          // 100 recurrent + 4 input-drive rows
#define KHALF   (KDIM / 2)   // 52 per K-half
#define NQ      (KHALF / 4)  // 13 quads per half
#define BTILE   4
#define NTHREADS 256
#define NBLOCKS (B_TOT / BTILE)   // 256
#define RSTRIDE 112          // padded row stride for Rt (floats)
#define ALPHA   0.01f
#define NSTD    0.1f

__device__ __forceinline__ float tanh_fast(float x) {
    float y;
    asm("tanh.approx.f32 %0, %1;" : "=f"(y) : "f"(x));
    return y;
}
__device__ __forceinline__ unsigned long long pack_pair(float lo, float hi) {
    unsigned long long r;
    asm("mov.b64 %0, {%1, %2};" : "=l"(r) : "f"(lo), "f"(hi));
    return r;
}
__device__ __forceinline__ void ffma2(unsigned long long& d,
                                      unsigned long long a,
                                      unsigned long long b) {
    asm("fma.rn.f32x2 %0, %1, %2, %0;" : "+l"(d) : "l"(a), "l"(b));
}
__device__ __forceinline__ float2 unpack2(unsigned long long v) {
    float2 f;
    asm("mov.b64 {%0, %1}, %2;" : "=f"(f.x), "=f"(f.y) : "l"(v));
    return f;
}

// Layout: 256 threads = (i, h); i = tid & 127 state row, h = tid >> 7 K-half.
// Warps 0-3: h=0 (own x, noise, r-publish). Warps 4-7: h=1 (u rows, partials).
__global__ void __launch_bounds__(NTHREADS, 2)
rnn_kernel(const float* __restrict__ input_seq,
           const float* __restrict__ noise,
           const float* __restrict__ J_w,
           const float* __restrict__ Bmat,
           const float* __restrict__ c_x,
           const float* __restrict__ Wout_w,
           const float* __restrict__ Wout_b,
           float* __restrict__ out)
{
    __shared__ __align__(16) float Rt[BTILE][RSTRIDE];   // Rt[b][j], j contiguous
    __shared__ __align__(16) float Spart[128][BTILE];    // h=1 partial sums
    __shared__ float warp_part[8][BTILE];                // epilogue partials

    const int tid = threadIdx.x;
    const int i   = tid & 127;     // state row
    const int h   = tid >> 7;      // K-half
    const int b0  = blockIdx.x * BTILE;
    const int jbase = h * KHALF;   // 0 or 52 (both 16B-aligned in floats)

    // This thread's 52 J entries (row i, K-half h), packed as 26 j-pairs.
    unsigned long long Jp[NQ * 2];
#pragma unroll
    for (int k = 0; k < NQ * 2; k++) {
        float lo = 0.0f, hi = 0.0f;
        if (i < HID) {
            const int j0 = jbase + 2 * k, j1 = j0 + 1;
            lo = (j0 < HID) ? J_w[i * HID + j0] : Bmat[(j0 - HID) * HID + i];
            hi = (j1 < HID) ? J_w[i * HID + j1] : Bmat[(j1 - HID) * HID + i];
        }
        Jp[k] = pack_pair(lo, hi);
    }
    const float ci = (h == 0 && i < HID) ? (ALPHA * c_x[i]) : 0.0f;

    float x[BTILE];
#pragma unroll
    for (int b = 0; b < BTILE; b++) x[b] = 0.0f;

    // Noise double buffers (h=0 rows only); u double buffers (h=1, i<16).
    float nA[BTILE], nB[BTILE];
    float uA = 0.0f, uB = 0.0f;
    {
        const float* np = noise + (size_t)b0 * HID + i;
        const bool ldn = (h == 0 && i < HID);
#pragma unroll
        for (int b = 0; b < BTILE; b++)
            nA[b] = ldn ? np[b * HID] : 0.0f;
        if (h == 1 && i < 16)
            uA = input_seq[((size_t)b0 + (i >> 2)) * 4 + (i & 3)];
    }

    for (int t = 0; t < T_STEPS; t++) {
        // ---- Phase 1: publish R. h=0 rows write r=tanh(x) at column i;
        //      h=1 lanes 0..15 write u at columns 100..103.
        const float ucur = (t & 1) ? uB : uA;
        if (h == 0 && i < HID) {
            Rt[0][i] = tanh_fast(x[0]);
            Rt[1][i] = tanh_fast(x[1]);
            Rt[2][i] = tanh_fast(x[2]);
            Rt[3][i] = tanh_fast(x[3]);
        }
        if (h == 1 && i < 16)
            Rt[i >> 2][HID + (i & 3)] = ucur;
        __syncthreads();   // B1: R visible (also: Spart reads of t-1 done)

        // ---- Prefetch next step's noise / u into the spare buffer.
        const int tn = (t + 1 < T_STEPS) ? (t + 1) : t;
        {
            const float* np = noise + ((size_t)tn * B_TOT + b0) * HID + i;
            const bool ldn = (h == 0 && i < HID);
            if ((t & 1) == 0) {
#pragma unroll
                for (int b = 0; b < BTILE; b++)
                    nB[b] = ldn ? np[b * HID] : 0.0f;
                if (h == 1 && i < 16)
                    uB = input_seq[((size_t)tn * B_TOT + b0 + (i >> 2)) * 4 + (i & 3)];
            } else {
#pragma unroll
                for (int b = 0; b < BTILE; b++)
                    nA[b] = ldn ? np[b * HID] : 0.0f;
                if (h == 1 && i < 16)
                    uA = input_seq[((size_t)tn * B_TOT + b0 + (i >> 2)) * 4 + (i & 3)];
            }
        }

        // ---- Phase 2: partial acc over this thread's K-half.
        //      acc[b] += (J[j],J[j+1]) . (R[j][b],R[j+1][b])
        unsigned long long acc0 = 0ull, acc1 = 0ull, acc2 = 0ull, acc3 = 0ull;
#pragma unroll
        for (int q = 0; q < NQ; q++) {
            ulonglong2 r0 = *(const ulonglong2*)&Rt[0][jbase + 4 * q];
            ulonglong2 r1 = *(const ulonglong2*)&Rt[1][jbase + 4 * q];
            ulonglong2 r2 = *(const ulonglong2*)&Rt[2][jbase + 4 * q];
            ulonglong2 r3 = *(const ulonglong2*)&Rt[3][jbase + 4 * q];
            const unsigned long long ja = Jp[2 * q];
            const unsigned long long jb = Jp[2 * q + 1];
            ffma2(acc0, r0.x, ja);
            ffma2(acc1, r1.x, ja);
            ffma2(acc2, r2.x, ja);
            ffma2(acc3, r3.x, ja);
            ffma2(acc0, r0.y, jb);
            ffma2(acc1, r1.y, jb);
            ffma2(acc2, r2.y, jb);
            ffma2(acc3, r3.y, jb);
        }

        // h=1 publishes its combined partials (float4, conflict-free).
        if (h == 1) {
            float2 a0 = unpack2(acc0), a1 = unpack2(acc1);
            float2 a2 = unpack2(acc2), a3 = unpack2(acc3);
            float4 p;
            p.x = a0.x + a0.y;  p.y = a1.x + a1.y;
            p.z = a2.x + a2.y;  p.w = a3.x + a3.y;
            *(float4*)&Spart[i][0] = p;
        }
        __syncthreads();   // B2: partials visible; all Rt reads complete

        // ---- Phase 3: h=0 combines halves and updates x (registers only).
        if (h == 0) {
            float2 a0 = unpack2(acc0), a1 = unpack2(acc1);
            float2 a2 = unpack2(acc2), a3 = unpack2(acc3);
            float4 p = *(const float4*)&Spart[i][0];
            float y[BTILE] = { a0.x + a0.y + p.x, a1.x + a1.y + p.y,
                               a2.x + a2.y + p.z, a3.x + a3.y + p.w };
            const float* ncur = (t & 1) ? nB : nA;
#pragma unroll
            for (int b = 0; b < BTILE; b++) {
                x[b] = fmaf(1.0f - ALPHA, x[b],
                       fmaf(ALPHA, y[b],
                       fmaf(ALPHA * NSTD, ncur[b], ci)));
            }
        }
    }

    // ---- Epilogue: out[b] = tanh(x_final[b]) . Wout + bias (deterministic).
    {
        const float w = (h == 0 && i < HID) ? Wout_w[i] : 0.0f;
        float part[BTILE];
#pragma unroll
        for (int b = 0; b < BTILE; b++)
            part[b] = (h == 0 && i < HID) ? w * tanhf(x[b]) : 0.0f;
#pragma unroll
        for (int off = 16; off > 0; off >>= 1) {
#pragma unroll
            for (int b = 0; b < BTILE; b++)
                part[b] += __shfl_xor_sync(0xFFFFFFFFu, part[b], off);
        }
        const int warp = tid >> 5;
        if ((tid & 31) == 0) {
#pragma unroll
            for (int b = 0; b < BTILE; b++)
                warp_part[warp][b] = part[b];
        }
        __syncthreads();
        if (tid < BTILE) {
            float s = warp_part[0][tid] + warp_part[1][tid]
                    + warp_part[2][tid] + warp_part[3][tid];
            out[b0 + tid] = s + Wout_b[0];
        }
    }
}

extern "C" void kernel_launch(void* const* d_in, const int* in_sizes, int n_in,
                              void* d_out, int out_size)
{
    const float* input_seq = (const float*)d_in[0];  // [750,1024,4]
    const float* noise     = (const float*)d_in[1];  // [750,1024,100]
    const float* J_w       = (const float*)d_in[2];  // [100,100]
    const float* Bmat      = (const float*)d_in[3];  // [4,100]
    const float* c_x       = (const float*)d_in[4];  // [100]
    const float* Wout_w    = (const float*)d_in[5];  // [1,100]
    const float* Wout_b    = (const float*)d_in[6];  // [1]
    float* out = (float*)d_out;                      // [1024]

    rnn_kernel<<<NBLOCKS, NTHREADS>>>(
        input_seq, noise, J_w, Bmat, c_x, Wout_w, Wout_b, out);
}